// round 16
// baseline (speedup 1.0000x reference)
#include <cuda_runtime.h>
#include <cuda_fp16.h>
#include <math.h>
#include <stdint.h>
#include <string.h>

// Problem constants
#define BB   2
#define SS   2048
#define HH   2048
#define NHH  16
#define HDD  128
#define LDD  512
#define MM   (BB*SS)     // 4096

#define QSCALE_C (0.08838834764831845f * 1.4426950408889634f)

// ---------------------------------------------------------------------------
// Scratch (static device globals — allocation-free)
// ---------------------------------------------------------------------------
__device__ __half g_qh[MM * (size_t)HH];
__device__ __half g_kh[MM * (size_t)HH];
__device__ __half g_vh[MM * (size_t)HH];
__device__ __half g_oh[MM * (size_t)HH];
__device__ __half g_xh[MM * (size_t)HH];
__device__ __half g_klath[MM * (size_t)LDD];
__device__ __half g_vlath[MM * (size_t)LDD];
__device__ __half g_wqh[HH * (size_t)HH];
__device__ __half g_woh[HH * (size_t)HH];
__device__ __half g_wklath[LDD * (size_t)HH];
__device__ __half g_wvlath[LDD * (size_t)HH];
__device__ __half g_wkh[HH * (size_t)LDD];
__device__ __half g_wvh[HH * (size_t)LDD];

// ---------------------------------------------------------------------------
// PTX helpers (baseline-PTX only)
// ---------------------------------------------------------------------------
__device__ __forceinline__ uint32_t smem_u32(const void* p) {
    uint32_t a;
    asm("{ .reg .u64 t; cvta.to.shared.u64 t, %1; cvt.u32.u64 %0, t; }"
        : "=r"(a) : "l"(p));
    return a;
}
__device__ __forceinline__ void cp_async16(uint32_t s, const void* g) {
    asm volatile("cp.async.cg.shared.global [%0], [%1], 16;" :: "r"(s), "l"(g));
}
#define CP_COMMIT() asm volatile("cp.async.commit_group;" ::: "memory")
#define CP_WAIT0()  asm volatile("cp.async.wait_group 0;" ::: "memory")
#define CP_WAIT1()  asm volatile("cp.async.wait_group 1;" ::: "memory")
#define SWZ128(o) ((o) ^ (((o) >> 3) & 0x70))

__device__ __forceinline__ void ldsm_x4(uint32_t* r, uint32_t addr) {
    asm volatile("ldmatrix.sync.aligned.m8n8.x4.shared.b16 {%0,%1,%2,%3}, [%4];"
        : "=r"(r[0]), "=r"(r[1]), "=r"(r[2]), "=r"(r[3]) : "r"(addr));
}
__device__ __forceinline__ void ldsm_x4_trans(uint32_t* r, uint32_t addr) {
    asm volatile("ldmatrix.sync.aligned.m8n8.x4.trans.shared.b16 {%0,%1,%2,%3}, [%4];"
        : "=r"(r[0]), "=r"(r[1]), "=r"(r[2]), "=r"(r[3]) : "r"(addr));
}
__device__ __forceinline__ void mma_f16(float* d, const uint32_t* a,
                                        const uint32_t* b) {
    asm volatile(
        "mma.sync.aligned.m16n8k16.row.col.f32.f16.f16.f32 "
        "{%0,%1,%2,%3}, {%4,%5,%6,%7}, {%8,%9}, {%0,%1,%2,%3};"
        : "+f"(d[0]), "+f"(d[1]), "+f"(d[2]), "+f"(d[3])
        : "r"(a[0]), "r"(a[1]), "r"(a[2]), "r"(a[3]), "r"(b[0]), "r"(b[1]));
}
__device__ __forceinline__ uint32_t packh(float e, float o) {
    uint32_t r;
    asm("cvt.rn.f16x2.f32 %0, %1, %2;" : "=r"(r) : "f"(o), "f"(e));
    return r;
}
// fast exp2, degree-4 (rel err ~4e-5, far below fp16 P quantization)
__device__ __forceinline__ float exp2p(float x) {
    x = fmaxf(x, -126.f);
    float n = rintf(x);
    float f = x - n;
    float p = 0.009618129107628477f;
    p = fmaf(p, f, 0.05550410866482158f);
    p = fmaf(p, f, 0.2402265069591007f);
    p = fmaf(p, f, 0.6931471805599453f);
    p = fmaf(p, f, 1.0f);
    return p * __int_as_float(((int)n + 127) << 23);
}

// ---------------------------------------------------------------------------
// GEMM core: 128x128 CTA tile, 128 threads = 4 warps (2x2), warp tile 64x64.
// BK=64, 3-stage cp.async.
// ---------------------------------------------------------------------------
__device__ __forceinline__ void load_tile(
    const __half* __restrict__ A, const __half* __restrict__ B,
    int Kp, int bm, int bn, int tid, uint32_t tbase, int kt, int stage)
{
    uint32_t abase = tbase + (uint32_t)stage * 32768u;
    uint32_t bbase = abase + 16384u;
    #pragma unroll
    for (int r = 0; r < 8; r++) {
        int idx = tid + 128 * r;          // 0..1023
        int row = idx >> 3;
        int c16 = idx & 7;
        uint32_t soff = SWZ128((uint32_t)(row * 128 + c16 * 16));
        cp_async16(abase + soff, A + (size_t)(bm + row) * Kp + kt * 64 + c16 * 8);
        cp_async16(bbase + soff, B + (size_t)(bn + row) * Kp + kt * 64 + c16 * 8);
    }
    CP_COMMIT();
}

__device__ __forceinline__ void gemm_core(
    const __half* __restrict__ A, const __half* __restrict__ B,
    int Kp, int bm, int bn, int tid, int wid, int lane, uint32_t tbase,
    float acc[4][8][4])
{
    const int wm = (wid & 1) * 64;
    const int wn = (wid >> 1) * 64;
    const int a_row   = wm + (lane & 15);
    const int a_chalf = lane >> 4;
    const int b_row   = wn + ((lane >> 4) << 3) + (lane & 7);
    const int b_chalf = (lane >> 3) & 1;

    const int niter = Kp / 64;
    load_tile(A, B, Kp, bm, bn, tid, tbase, 0, 0);
    load_tile(A, B, Kp, bm, bn, tid, tbase, 1, 1);

    int cs = 0, ls = 2;
    for (int it = 0; it < niter; it++) {
        CP_WAIT1();
        __syncthreads();
        if (it + 2 < niter) {
            load_tile(A, B, Kp, bm, bn, tid, tbase, it + 2, ls);
            ls = (ls == 2) ? 0 : ls + 1;
        }
        const uint32_t a_s = tbase + (uint32_t)cs * 32768u;
        const uint32_t b_s = a_s + 16384u;
        cs = (cs == 2) ? 0 : cs + 1;

        #pragma unroll
        for (int s = 0; s < 4; s++) {
            uint32_t af[4][4];
            #pragma unroll
            for (int mt = 0; mt < 4; mt++) {
                int row = a_row + mt * 16;
                int ch  = (2 * s + a_chalf) ^ (row & 7);
                ldsm_x4(af[mt], a_s + (uint32_t)(row * 128 + ch * 16));
            }
            uint32_t bf[4][4];
            #pragma unroll
            for (int nt = 0; nt < 4; nt++) {
                int row = b_row + nt * 16;
                int ch  = (2 * s + b_chalf) ^ (row & 7);
                ldsm_x4(bf[nt], b_s + (uint32_t)(row * 128 + ch * 16));
            }
            #pragma unroll
            for (int mt = 0; mt < 4; mt++)
                #pragma unroll
                for (int n8 = 0; n8 < 8; n8++)
                    mma_f16(acc[mt][n8], af[mt], &bf[n8 >> 1][(n8 & 1) * 2]);
        }
    }
}

#define ACC_INIT(acc) do { \
    _Pragma("unroll") \
    for (int mt = 0; mt < 4; mt++) \
        _Pragma("unroll") \
        for (int n8 = 0; n8 < 8; n8++) \
            _Pragma("unroll") \
            for (int j = 0; j < 4; j++) (acc)[mt][n8][j] = 0.f; \
} while (0)

// ---------------------------------------------------------------------------
// Merged projection kernel: q (scaled) / klat / vlat — all single hi plane.
// 768 tiles: [0,512) q, [512,640) klat, [640,768) vlat. Kp = HH.
// ---------------------------------------------------------------------------
__global__ void __launch_bounds__(128, 2) proj_kernel(
    const __half* __restrict__ xh,
    const __half* __restrict__ wqh,
    const __half* __restrict__ wklath,
    const __half* __restrict__ wvlath,
    const float* __restrict__ bq,
    __half* __restrict__ qh,
    __half* __restrict__ klath, __half* __restrict__ vlath)
{
    extern __shared__ char dsm[];
    const uint32_t tbase = (smem_u32(dsm) + 1023u) & ~1023u;
    const int tid  = threadIdx.x;
    const int wid  = tid >> 5;
    const int lane = tid & 31;

    const __half* B;
    __half* O;
    int N, mode, bm, bn;
    const int bid = blockIdx.x;
    if (bid < 512) {
        B = wqh; O = qh; N = 2048; mode = 1;
        bm = (bid >> 4) * 128; bn = (bid & 15) * 128;
    } else {
        int t = bid - 512;
        if (t < 128) { B = wklath; O = klath; }
        else         { B = wvlath; O = vlath; t -= 128; }
        N = 512; mode = 2;
        bm = (t >> 2) * 128; bn = (t & 3) * 128;
    }

    float acc[4][8][4];
    ACC_INIT(acc);
    gemm_core(xh, B, HH, bm, bn, tid, wid, lane, tbase, acc);

    const int wm = (wid & 1) * 64;
    const int wn = (wid >> 1) * 64;
    #pragma unroll
    for (int mt = 0; mt < 4; mt++) {
        const int r0 = bm + wm + mt * 16 + (lane >> 2);
        #pragma unroll
        for (int n8 = 0; n8 < 8; n8++) {
            const int c0 = bn + wn + n8 * 8 + (lane & 3) * 2;
            float2 v0 = make_float2(acc[mt][n8][0], acc[mt][n8][1]);
            float2 v1 = make_float2(acc[mt][n8][2], acc[mt][n8][3]);
            if (mode == 1) {
                float b0 = bq[c0], b1 = bq[c0 + 1];
                v0.x = (v0.x + b0) * QSCALE_C; v0.y = (v0.y + b1) * QSCALE_C;
                v1.x = (v1.x + b0) * QSCALE_C; v1.y = (v1.y + b1) * QSCALE_C;
            }
            *(uint32_t*)(O + (size_t)r0 * N + c0)       = packh(v0.x, v0.y);
            *(uint32_t*)(O + (size_t)(r0 + 8) * N + c0) = packh(v1.x, v1.y);
        }
    }
}

// ---------------------------------------------------------------------------
// Merged k+v kernel: [0,512) k, [512,1024) v. Kp = LDD (single term).
// ---------------------------------------------------------------------------
__global__ void __launch_bounds__(128, 2) kv_kernel(
    const __half* __restrict__ klath, const __half* __restrict__ vlath,
    const __half* __restrict__ wkh,   const __half* __restrict__ wvh,
    __half* __restrict__ kh, __half* __restrict__ vh)
{
    extern __shared__ char dsm[];
    const uint32_t tbase = (smem_u32(dsm) + 1023u) & ~1023u;
    const int tid  = threadIdx.x;
    const int wid  = tid >> 5;
    const int lane = tid & 31;

    const __half *A, *B;
    __half* O;
    int t = blockIdx.x;
    if (t < 512) { A = klath; B = wkh; O = kh; }
    else         { A = vlath; B = wvh; O = vh; t -= 512; }
    const int bm = (t >> 4) * 128;
    const int bn = (t & 15) * 128;
    const int N = 2048;

    float acc[4][8][4];
    ACC_INIT(acc);
    gemm_core(A, B, LDD, bm, bn, tid, wid, lane, tbase, acc);

    const int wm = (wid & 1) * 64;
    const int wn = (wid >> 1) * 64;
    #pragma unroll
    for (int mt = 0; mt < 4; mt++) {
        const int r0 = bm + wm + mt * 16 + (lane >> 2);
        #pragma unroll
        for (int n8 = 0; n8 < 8; n8++) {
            const int c0 = bn + wn + n8 * 8 + (lane & 3) * 2;
            *(uint32_t*)(O + (size_t)r0 * N + c0)       = packh(acc[mt][n8][0], acc[mt][n8][1]);
            *(uint32_t*)(O + (size_t)(r0 + 8) * N + c0) = packh(acc[mt][n8][2], acc[mt][n8][3]);
        }
    }
}

// ---------------------------------------------------------------------------
// Output projection: out = oh @ woh^T + bo (fp32 out), Kp = HH
// ---------------------------------------------------------------------------
__global__ void __launch_bounds__(128, 2) wo_kernel(
    const __half* __restrict__ oh, const __half* __restrict__ woh,
    const float* __restrict__ bo, float* __restrict__ C)
{
    extern __shared__ char dsm[];
    const uint32_t tbase = (smem_u32(dsm) + 1023u) & ~1023u;
    const int tid  = threadIdx.x;
    const int wid  = tid >> 5;
    const int lane = tid & 31;
    const int bm = blockIdx.y * 128;
    const int bn = blockIdx.x * 128;
    const int N = 2048;

    float acc[4][8][4];
    ACC_INIT(acc);
    gemm_core(oh, woh, HH, bm, bn, tid, wid, lane, tbase, acc);

    const int wm = (wid & 1) * 64;
    const int wn = (wid >> 1) * 64;
    #pragma unroll
    for (int mt = 0; mt < 4; mt++) {
        const int r0 = bm + wm + mt * 16 + (lane >> 2);
        #pragma unroll
        for (int n8 = 0; n8 < 8; n8++) {
            const int c0 = bn + wn + n8 * 8 + (lane & 3) * 2;
            float b0 = bo[c0], b1 = bo[c0 + 1];
            float2 v0 = make_float2(acc[mt][n8][0] + b0, acc[mt][n8][1] + b1);
            float2 v1 = make_float2(acc[mt][n8][2] + b0, acc[mt][n8][3] + b1);
            *(float2*)(C + (size_t)r0 * N + c0)       = v0;
            *(float2*)(C + (size_t)(r0 + 8) * N + c0) = v1;
        }
    }
}

// ---------------------------------------------------------------------------
// Input conversions
// ---------------------------------------------------------------------------
__global__ void cast_rows_kernel(const float* __restrict__ in,
                                 __half* __restrict__ out, int total2)
{
    int i2 = blockIdx.x * blockDim.x + threadIdx.x;
    if (i2 >= total2) return;
    float2 v = ((const float2*)in)[i2];
    ((__half2*)out)[i2] = __floats2half2_rn(v.x, v.y);
}

// merged weight transpose+cast: fp32 [K,N] -> fp16 [N,K], all 6 weights
__global__ void splitw_kernel(
    const float* __restrict__ wq, const float* __restrict__ wklat,
    const float* __restrict__ wvlat, const float* __restrict__ wk,
    const float* __restrict__ wv, const float* __restrict__ wo,
    __half* __restrict__ wqh, __half* __restrict__ wklath,
    __half* __restrict__ wvlath, __half* __restrict__ wkh,
    __half* __restrict__ wvh, __half* __restrict__ woh)
{
    __shared__ float t[32][33];
    int l = blockIdx.x;
    const float* in; __half* out; int K, N, tt;
    if (l < 4096)      { in = wq;    out = wqh;    K = 2048; N = 2048; tt = l; }
    else if (l < 5120) { in = wklat; out = wklath; K = 2048; N = 512;  tt = l - 4096; }
    else if (l < 6144) { in = wvlat; out = wvlath; K = 2048; N = 512;  tt = l - 5120; }
    else if (l < 7168) { in = wk;    out = wkh;    K = 512;  N = 2048; tt = l - 6144; }
    else if (l < 8192) { in = wv;    out = wvh;    K = 512;  N = 2048; tt = l - 7168; }
    else               { in = wo;    out = woh;    K = 2048; N = 2048; tt = l - 8192; }
    int nnb = N >> 5;
    int k0 = (tt / nnb) * 32, n0 = (tt % nnb) * 32;
    int tx = threadIdx.x, ty = threadIdx.y;
    #pragma unroll
    for (int i = 0; i < 32; i += 8)
        t[ty + i][tx] = in[(size_t)(k0 + ty + i) * N + n0 + tx];
    __syncthreads();
    #pragma unroll
    for (int i = 0; i < 32; i += 8) {
        int n = ty + i;
        out[(size_t)(n0 + n) * K + k0 + tx] = __float2half_rn(t[tx][n]);
    }
}

// ---------------------------------------------------------------------------
// Tensor-core flash attention (causal), fp16, TQ=64, 128 thr = 4 warps x 16
// q-rows, 2 CTAs/SM. Split-wait pipeline: K double-buffered, V single buffer.
//   pending groups invariant at loop top: {K(kt)}, {V(kt)}
//   wait1 -> K ready -> scores (V in flight)
//   prefetch K(kt+1), commit -> softmax (K' in flight)
//   wait1 -> V ready -> PV (K' in flight)
//   sync -> issue V(kt+1), commit
// smem: Qh(16K)+KB0(32K)+KB1(32K)+VB(32K) = 112KB exactly (8KB-granular;
// 2x112K = 224K <= 228K carveout -> 2 CTAs/SM).
// ---------------------------------------------------------------------------
#define SM_QH 0u
#define SM_KB(b) (16384u + (uint32_t)(b) * 32768u)
#define SM_VB 81920u

__global__ void __launch_bounds__(128, 2) mla_attn_tc_kernel(
    const __half* __restrict__ Qh,
    const __half* __restrict__ Kh, const __half* __restrict__ Vh,
    __half* __restrict__ Oh)
{
    extern __shared__ char dsm[];
    const uint32_t sb = smem_u32(dsm);

    const int tid  = threadIdx.x;
    const int lane = tid & 31;
    const int w    = tid >> 5;            // 0..3
    const int bh   = blockIdx.y;
    const int b    = bh >> 4;
    const int h    = bh & 15;
    const int qt   = gridDim.x - 1 - blockIdx.x;   // heavy tiles first

    const size_t qrow0 = (size_t)b * SS + (size_t)qt * 64;
    const size_t hcol  = (size_t)h * HDD;
    const int ktmax = ((qt + 1) * 64 - 1) >> 7;    // last k-tile (128-wide)
    const size_t kvbase = (size_t)b * SS;

    // prologue group A: Q (1024 chunks) + K0 (2048 chunks)
    #pragma unroll
    for (int i = 0; i < 8; i++) {
        int idx = tid + 128 * i;          // 0..1023
        int r   = idx >> 4;               // 0..63
        int d   = (idx & 15) * 8;
        uint32_t off = (uint32_t)(d >> 6) * 8192u
                     + SWZ128((uint32_t)(r * 128 + (d & 63) * 2));
        cp_async16(sb + SM_QH + off, Qh + (qrow0 + r) * HH + hcol + d);
    }
    #pragma unroll
    for (int i = 0; i < 16; i++) {
        int idx = tid + 128 * i;          // 0..2047
        int r   = idx >> 4;               // 0..127
        int d   = (idx & 15) * 8;
        uint32_t off = (uint32_t)(d >> 6) * 16384u
                     + SWZ128((uint32_t)(r * 128 + (d & 63) * 2));
        cp_async16(sb + SM_KB(0) + off, Kh + (kvbase + r) * HH + hcol + d);
    }
    CP_COMMIT();
    // prologue group B: V0
    #pragma unroll
    for (int i = 0; i < 16; i++) {
        int idx = tid + 128 * i;
        int r   = idx >> 4;
        int d   = (idx & 15) * 8;
        uint32_t off = (uint32_t)(d >> 6) * 16384u
                     + SWZ128((uint32_t)(r * 128 + (d & 63) * 2));
        cp_async16(sb + SM_VB + off, Vh + (kvbase + r) * HH + hcol + d);
    }
    CP_COMMIT();

    float m2[2] = {-1e30f, -1e30f};
    float l2[2] = {0.f, 0.f};
    float ov[16][4];
    #pragma unroll
    for (int j = 0; j < 16; j++)
        ov[j][0] = ov[j][1] = ov[j][2] = ov[j][3] = 0.f;

    const int a_row  = 16 * w + (lane & 15);       // < 64
    const int a_ch   = lane >> 4;
    const int b_rowb = ((lane >> 4) << 3) + (lane & 7);
    const int b_ch   = (lane >> 3) & 1;
    const int v_row  = (lane & 7) + ((lane >> 3) & 1) * 8;
    const int qlocA  = 16 * w + (lane >> 2);
    const int qgA    = qt * 64 + qlocA;            // global q row (A); B = +8

    for (int kt = 0; kt <= ktmax; kt++) {
        // pending: {K(kt)}, {V(kt)} -> wait K
        CP_WAIT1();
        __syncthreads();

        const uint32_t kbs = sb + SM_KB(kt & 1);

        // ---- scores: S = Qh·Kh^T (V(kt) load in flight underneath) ----
        float sc[16][4];
        #pragma unroll
        for (int j = 0; j < 16; j++)
            sc[j][0] = sc[j][1] = sc[j][2] = sc[j][3] = 0.f;

        #pragma unroll
        for (int kc = 0; kc < 8; kc++) {
            uint32_t ah[4];
            {
                int ch = (2 * (kc & 3) + a_ch) ^ (a_row & 7);
                uint32_t off = (uint32_t)(kc >> 2) * 8192u
                             + (uint32_t)(a_row * 128 + ch * 16);
                ldsm_x4(ah, sb + SM_QH + off);
            }
            #pragma unroll
            for (int half = 0; half < 2; half++) {
                uint32_t bh4[4][4];
                #pragma unroll
                for (int nt4 = 0; nt4 < 4; nt4++) {
                    int row = (half * 4 + nt4) * 16 + b_rowb;
                    int ch = (2 * (kc & 3) + b_ch) ^ (row & 7);
                    uint32_t off = (uint32_t)(kc >> 2) * 16384u
                                 + (uint32_t)(row * 128 + ch * 16);
                    ldsm_x4(bh4[nt4], kbs + off);
                }
                #pragma unroll
                for (int nt4 = 0; nt4 < 4; nt4++) {
                    int j0 = (half * 4 + nt4) * 2;
                    mma_f16(sc[j0],     ah, &bh4[nt4][0]);
                    mma_f16(sc[j0 + 1], ah, &bh4[nt4][2]);
                }
            }
        }

        // ---- prefetch K(kt+1) into other K buffer (hidden behind softmax/PV)
        if (kt < ktmax) {
            const size_t krow1 = kvbase + (size_t)(kt + 1) * 128;
            const uint32_t kb1 = SM_KB((kt + 1) & 1);
            #pragma unroll
            for (int i = 0; i < 16; i++) {
                int idx = tid + 128 * i;
                int r   = idx >> 4;
                int d   = (idx & 15) * 8;
                uint32_t off = (uint32_t)(d >> 6) * 16384u
                             + SWZ128((uint32_t)(r * 128 + (d & 63) * 2));
                cp_async16(sb + kb1 + off, Kh + (krow1 + r) * HH + hcol + d);
            }
        }
        CP_COMMIT();   // empty group when kt==ktmax keeps accounting uniform

        // ---- causal mask (last tile only) ----
        if (kt == ktmax) {
            #pragma unroll
            for (int j = 0; j < 16; j++) {
                int kkg = kt * 128 + 8 * j + 2 * (lane & 3);
                #pragma unroll
                for (int c = 0; c < 2; c++) {
                    if (kkg + c > qgA)     sc[j][c]     = -1e30f;
                    if (kkg + c > qgA + 8) sc[j][2 + c] = -1e30f;
                }
            }
        }

        // ---- online softmax (base-2 domain) ----
        {
            float mA = -1e30f, mB = -1e30f;
            #pragma unroll
            for (int j = 0; j < 16; j++) {
                mA = fmaxf(mA, fmaxf(sc[j][0], sc[j][1]));
                mB = fmaxf(mB, fmaxf(sc[j][2], sc[j][3]));
            }
            mA = fmaxf(mA, __shfl_xor_sync(0xffffffffu, mA, 1));
            mA = fmaxf(mA, __shfl_xor_sync(0xffffffffu, mA, 2));
            mB = fmaxf(mB, __shfl_xor_sync(0xffffffffu, mB, 1));
            mB = fmaxf(mB, __shfl_xor_sync(0xffffffffu, mB, 2));
            float nmA = fmaxf(m2[0], mA), nmB = fmaxf(m2[1], mB);
            float aA = exp2p(m2[0] - nmA), aB = exp2p(m2[1] - nmB);
            float sA = 0.f, sB = 0.f;
            #pragma unroll
            for (int j = 0; j < 16; j++) {
                sc[j][0] = exp2p(sc[j][0] - nmA);
                sc[j][1] = exp2p(sc[j][1] - nmA);
                sc[j][2] = exp2p(sc[j][2] - nmB);
                sc[j][3] = exp2p(sc[j][3] - nmB);
                sA += sc[j][0] + sc[j][1];
                sB += sc[j][2] + sc[j][3];
            }
            sA += __shfl_xor_sync(0xffffffffu, sA, 1);
            sA += __shfl_xor_sync(0xffffffffu, sA, 2);
            sB += __shfl_xor_sync(0xffffffffu, sB, 1);
            sB += __shfl_xor_sync(0xffffffffu, sB, 2);
            l2[0] = l2[0] * aA + sA;
            l2[1] = l2[1] * aB + sB;
            m2[0] = nmA; m2[1] = nmB;
            #pragma unroll
            for (int j = 0; j < 16; j++) {
                ov[j][0] *= aA; ov[j][1] *= aA;
                ov[j][2] *= aB; ov[j][3] *= aB;
            }
        }

        // pending: {V(kt)}, {K(kt+1)} -> wait V
        CP_WAIT1();
        __syncthreads();

        // ---- O += Ph·Vh (K(kt+1) load in flight underneath) ----
        #pragma unroll
        for (int kc = 0; kc < 8; kc++) {
            int j0 = 2 * kc;
            uint32_t ph[4];
            #pragma unroll
            for (int u = 0; u < 2; u++)
                #pragma unroll
                for (int t = 0; t < 2; t++)
                    ph[2 * u + t] = packh(sc[j0 + u][2 * t], sc[j0 + u][2 * t + 1]);
            #pragma unroll
            for (int dt = 0; dt < 8; dt++) {
                uint32_t vh4[4];
                int row = kc * 16 + v_row;
                int dloc = (dt * 16) & 63;
                int ch = ((dloc >> 3) + (lane >> 4)) ^ (row & 7);
                uint32_t off = (uint32_t)(dt >> 2) * 16384u
                             + (uint32_t)(row * 128 + ch * 16);
                ldsm_x4_trans(vh4, sb + SM_VB + off);
                int oj = 2 * dt;
                mma_f16(ov[oj],     ph, &vh4[0]);
                mma_f16(ov[oj + 1], ph, &vh4[2]);
            }
        }

        // all warps done reading VB, then refill with V(kt+1)
        __syncthreads();
        if (kt < ktmax) {
            const size_t krow1 = kvbase + (size_t)(kt + 1) * 128;
            #pragma unroll
            for (int i = 0; i < 16; i++) {
                int idx = tid + 128 * i;
                int r   = idx >> 4;
                int d   = (idx & 15) * 8;
                uint32_t off = (uint32_t)(d >> 6) * 16384u
                             + SWZ128((uint32_t)(r * 128 + (d & 63) * 2));
                cp_async16(sb + SM_VB + off, Vh + (krow1 + r) * HH + hcol + d);
            }
        }
        CP_COMMIT();   // invariant restored: {K(kt+1)}, {V(kt+1)}
    }

    // ---- epilogue: normalize and write oh ----
    {
        float i0 = 1.f / l2[0], i1 = 1.f / l2[1];
        size_t rA = qrow0 + qlocA;
        __half* row0 = Oh + rA * (size_t)HH + hcol;
        __half* row1 = Oh + (rA + 8) * (size_t)HH + hcol;
        #pragma unroll
        for (int j = 0; j < 16; j++) {
            int c = 8 * j + 2 * (lane & 3);
            *(uint32_t*)(row0 + c) = packh(ov[j][0] * i0, ov[j][1] * i0);
            *(uint32_t*)(row1 + c) = packh(ov[j][2] * i1, ov[j][3] * i1);
        }
    }
}

// ---------------------------------------------------------------------------
// launch
// ---------------------------------------------------------------------------
extern "C" void kernel_launch(void* const* d_in, const int* in_sizes, int n_in,
                              void* d_out, int out_size)
{
    (void)in_sizes; (void)n_in; (void)out_size;
    const float* x      = (const float*)d_in[0];
    const float* wq     = (const float*)d_in[1];
    const float* bq     = (const float*)d_in[2];
    const float* wk_lat = (const float*)d_in[3];
    const float* wv_lat = (const float*)d_in[4];
    const float* wk     = (const float*)d_in[5];
    const float* wv     = (const float*)d_in[6];
    const float* wo     = (const float*)d_in[7];
    const float* bo     = (const float*)d_in[8];
    float* out = (float*)d_out;

    __half *qh, *kh, *vh, *oh, *xh;
    cudaGetSymbolAddress((void**)&qh, g_qh);
    cudaGetSymbolAddress((void**)&kh, g_kh);
    cudaGetSymbolAddress((void**)&vh, g_vh);
    cudaGetSymbolAddress((void**)&oh, g_oh);
    cudaGetSymbolAddress((void**)&xh, g_xh);

    __half *klath, *vlath, *wqh, *woh, *wklath, *wvlath, *wkh, *wvh;
    cudaGetSymbolAddress((void**)&klath,  g_klath);
    cudaGetSymbolAddress((void**)&vlath,  g_vlath);
    cudaGetSymbolAddress((void**)&wqh,    g_wqh);
    cudaGetSymbolAddress((void**)&woh,    g_woh);
    cudaGetSymbolAddress((void**)&wklath, g_wklath);
    cudaGetSymbolAddress((void**)&wvlath, g_wvlath);
    cudaGetSymbolAddress((void**)&wkh,    g_wkh);
    cudaGetSymbolAddress((void**)&wvh,    g_wvh);

    const int smem_gemm = 3 * 32768 + 1024;
    cudaFuncSetAttribute(proj_kernel,
                         cudaFuncAttributeMaxDynamicSharedMemorySize, smem_gemm);
    cudaFuncSetAttribute(kv_kernel,
                         cudaFuncAttributeMaxDynamicSharedMemorySize, smem_gemm);
    cudaFuncSetAttribute(wo_kernel,
                         cudaFuncAttributeMaxDynamicSharedMemorySize, smem_gemm);
    const int smem_attn = 112 * 1024;   // exactly 8KB-granular, 2 CTAs/SM
    cudaFuncSetAttribute(mla_attn_tc_kernel,
                         cudaFuncAttributeMaxDynamicSharedMemorySize, smem_attn);

    // ---- input conversions ----
    {
        int tot = MM * HH / 2;
        cast_rows_kernel<<<(tot + 255) / 256, 256>>>(x, xh, tot);
    }
    splitw_kernel<<<12288, dim3(32, 8)>>>(
        wq, wk_lat, wv_lat, wk, wv, wo,
        wqh, wklath, wvlath, wkh, wvh, woh);

    // ---- merged projections: q + klat + vlat (K = 2048) ----
    proj_kernel<<<768, 128, smem_gemm>>>(
        xh, wqh, wklath, wvlath, bq, qh, klath, vlath);

    // ---- merged k + v (K = 512) ----
    kv_kernel<<<1024, 128, smem_gemm>>>(klath, vlath, wkh, wvh, kh, vh);

    // ---- attention (TQ=64, 2 CTAs/SM, split-wait K/K'/V pipeline) ----
    mla_attn_tc_kernel<<<dim3(SS / 64, BB * NHH), 128, smem_attn>>>(
        qh, kh, vh, oh);

    // ---- output projection (K = 2048) ----
    wo_kernel<<<dim3(HH / 128, MM / 128), 128, smem_gemm>>>(oh, woh, bo, out);
}

// round 17
// speedup vs baseline: 1.0411x; 1.0411x over previous
#include <cuda_runtime.h>
#include <cuda_fp16.h>
#include <math.h>
#include <stdint.h>
#include <string.h>

// Problem constants
#define BB   2
#define SS   2048
#define HH   2048
#define NHH  16
#define HDD  128
#define LDD  512
#define MM   (BB*SS)     // 4096

#define QSCALE_C (0.08838834764831845f * 1.4426950408889634f)

// ---------------------------------------------------------------------------
// Scratch (static device globals — allocation-free)
// ---------------------------------------------------------------------------
__device__ __half g_qh[MM * (size_t)HH];
__device__ __half g_kh[MM * (size_t)HH];
__device__ __half g_vh[MM * (size_t)HH];
__device__ __half g_oh[MM * (size_t)HH];
__device__ __half g_xh[MM * (size_t)HH];
__device__ __half g_klath[MM * (size_t)LDD];
__device__ __half g_vlath[MM * (size_t)LDD];
__device__ __half g_wqh[HH * (size_t)HH];
__device__ __half g_woh[HH * (size_t)HH];
__device__ __half g_wklath[LDD * (size_t)HH];
__device__ __half g_wvlath[LDD * (size_t)HH];
__device__ __half g_wkh[HH * (size_t)LDD];
__device__ __half g_wvh[HH * (size_t)LDD];

// ---------------------------------------------------------------------------
// PTX helpers (baseline-PTX only)
// ---------------------------------------------------------------------------
__device__ __forceinline__ uint32_t smem_u32(const void* p) {
    uint32_t a;
    asm("{ .reg .u64 t; cvta.to.shared.u64 t, %1; cvt.u32.u64 %0, t; }"
        : "=r"(a) : "l"(p));
    return a;
}
__device__ __forceinline__ void cp_async16(uint32_t s, const void* g) {
    asm volatile("cp.async.cg.shared.global [%0], [%1], 16;" :: "r"(s), "l"(g));
}
#define CP_COMMIT() asm volatile("cp.async.commit_group;" ::: "memory")
#define CP_WAIT0()  asm volatile("cp.async.wait_group 0;" ::: "memory")
#define CP_WAIT1()  asm volatile("cp.async.wait_group 1;" ::: "memory")
#define SWZ128(o) ((o) ^ (((o) >> 3) & 0x70))

__device__ __forceinline__ void ldsm_x4(uint32_t* r, uint32_t addr) {
    asm volatile("ldmatrix.sync.aligned.m8n8.x4.shared.b16 {%0,%1,%2,%3}, [%4];"
        : "=r"(r[0]), "=r"(r[1]), "=r"(r[2]), "=r"(r[3]) : "r"(addr));
}
__device__ __forceinline__ void ldsm_x4_trans(uint32_t* r, uint32_t addr) {
    asm volatile("ldmatrix.sync.aligned.m8n8.x4.trans.shared.b16 {%0,%1,%2,%3}, [%4];"
        : "=r"(r[0]), "=r"(r[1]), "=r"(r[2]), "=r"(r[3]) : "r"(addr));
}
__device__ __forceinline__ void mma_f16(float* d, const uint32_t* a,
                                        const uint32_t* b) {
    asm volatile(
        "mma.sync.aligned.m16n8k16.row.col.f32.f16.f16.f32 "
        "{%0,%1,%2,%3}, {%4,%5,%6,%7}, {%8,%9}, {%0,%1,%2,%3};"
        : "+f"(d[0]), "+f"(d[1]), "+f"(d[2]), "+f"(d[3])
        : "r"(a[0]), "r"(a[1]), "r"(a[2]), "r"(a[3]), "r"(b[0]), "r"(b[1]));
}
__device__ __forceinline__ uint32_t packh(float e, float o) {
    uint32_t r;
    asm("cvt.rn.f16x2.f32 %0, %1, %2;" : "=r"(r) : "f"(o), "f"(e));
    return r;
}
// fast exp2, degree-4 (rel err ~4e-5, far below fp16 P quantization)
__device__ __forceinline__ float exp2p(float x) {
    x = fmaxf(x, -126.f);
    float n = rintf(x);
    float f = x - n;
    float p = 0.009618129107628477f;
    p = fmaf(p, f, 0.05550410866482158f);
    p = fmaf(p, f, 0.2402265069591007f);
    p = fmaf(p, f, 0.6931471805599453f);
    p = fmaf(p, f, 1.0f);
    return p * __int_as_float(((int)n + 127) << 23);
}

// ---------------------------------------------------------------------------
// GEMM core: 128x128 CTA tile, 128 threads = 4 warps (2x2), warp tile 64x64.
// BK=64, 3-stage cp.async.
// ---------------------------------------------------------------------------
__device__ __forceinline__ void load_tile(
    const __half* __restrict__ A, const __half* __restrict__ B,
    int Kp, int bm, int bn, int tid, uint32_t tbase, int kt, int stage)
{
    uint32_t abase = tbase + (uint32_t)stage * 32768u;
    uint32_t bbase = abase + 16384u;
    #pragma unroll
    for (int r = 0; r < 8; r++) {
        int idx = tid + 128 * r;          // 0..1023
        int row = idx >> 3;
        int c16 = idx & 7;
        uint32_t soff = SWZ128((uint32_t)(row * 128 + c16 * 16));
        cp_async16(abase + soff, A + (size_t)(bm + row) * Kp + kt * 64 + c16 * 8);
        cp_async16(bbase + soff, B + (size_t)(bn + row) * Kp + kt * 64 + c16 * 8);
    }
    CP_COMMIT();
}

__device__ __forceinline__ void gemm_core(
    const __half* __restrict__ A, const __half* __restrict__ B,
    int Kp, int bm, int bn, int tid, int wid, int lane, uint32_t tbase,
    float acc[4][8][4])
{
    const int wm = (wid & 1) * 64;
    const int wn = (wid >> 1) * 64;
    const int a_row   = wm + (lane & 15);
    const int a_chalf = lane >> 4;
    const int b_row   = wn + ((lane >> 4) << 3) + (lane & 7);
    const int b_chalf = (lane >> 3) & 1;

    const int niter = Kp / 64;
    load_tile(A, B, Kp, bm, bn, tid, tbase, 0, 0);
    load_tile(A, B, Kp, bm, bn, tid, tbase, 1, 1);

    int cs = 0, ls = 2;
    for (int it = 0; it < niter; it++) {
        CP_WAIT1();
        __syncthreads();
        if (it + 2 < niter) {
            load_tile(A, B, Kp, bm, bn, tid, tbase, it + 2, ls);
            ls = (ls == 2) ? 0 : ls + 1;
        }
        const uint32_t a_s = tbase + (uint32_t)cs * 32768u;
        const uint32_t b_s = a_s + 16384u;
        cs = (cs == 2) ? 0 : cs + 1;

        #pragma unroll
        for (int s = 0; s < 4; s++) {
            uint32_t af[4][4];
            #pragma unroll
            for (int mt = 0; mt < 4; mt++) {
                int row = a_row + mt * 16;
                int ch  = (2 * s + a_chalf) ^ (row & 7);
                ldsm_x4(af[mt], a_s + (uint32_t)(row * 128 + ch * 16));
            }
            uint32_t bf[4][4];
            #pragma unroll
            for (int nt = 0; nt < 4; nt++) {
                int row = b_row + nt * 16;
                int ch  = (2 * s + b_chalf) ^ (row & 7);
                ldsm_x4(bf[nt], b_s + (uint32_t)(row * 128 + ch * 16));
            }
            #pragma unroll
            for (int mt = 0; mt < 4; mt++)
                #pragma unroll
                for (int n8 = 0; n8 < 8; n8++)
                    mma_f16(acc[mt][n8], af[mt], &bf[n8 >> 1][(n8 & 1) * 2]);
        }
    }
}

#define ACC_INIT(acc) do { \
    _Pragma("unroll") \
    for (int mt = 0; mt < 4; mt++) \
        _Pragma("unroll") \
        for (int n8 = 0; n8 < 8; n8++) \
            _Pragma("unroll") \
            for (int j = 0; j < 4; j++) (acc)[mt][n8][j] = 0.f; \
} while (0)

// ---------------------------------------------------------------------------
// Merged projection kernel: q (scaled) / klat / vlat — all single hi plane.
// 768 tiles: [0,512) q, [512,640) klat, [640,768) vlat. Kp = HH.
// ---------------------------------------------------------------------------
__global__ void __launch_bounds__(128, 2) proj_kernel(
    const __half* __restrict__ xh,
    const __half* __restrict__ wqh,
    const __half* __restrict__ wklath,
    const __half* __restrict__ wvlath,
    const float* __restrict__ bq,
    __half* __restrict__ qh,
    __half* __restrict__ klath, __half* __restrict__ vlath)
{
    extern __shared__ char dsm[];
    const uint32_t tbase = (smem_u32(dsm) + 1023u) & ~1023u;
    const int tid  = threadIdx.x;
    const int wid  = tid >> 5;
    const int lane = tid & 31;

    const __half* B;
    __half* O;
    int N, mode, bm, bn;
    const int bid = blockIdx.x;
    if (bid < 512) {
        B = wqh; O = qh; N = 2048; mode = 1;
        bm = (bid >> 4) * 128; bn = (bid & 15) * 128;
    } else {
        int t = bid - 512;
        if (t < 128) { B = wklath; O = klath; }
        else         { B = wvlath; O = vlath; t -= 128; }
        N = 512; mode = 2;
        bm = (t >> 2) * 128; bn = (t & 3) * 128;
    }

    float acc[4][8][4];
    ACC_INIT(acc);
    gemm_core(xh, B, HH, bm, bn, tid, wid, lane, tbase, acc);

    const int wm = (wid & 1) * 64;
    const int wn = (wid >> 1) * 64;
    #pragma unroll
    for (int mt = 0; mt < 4; mt++) {
        const int r0 = bm + wm + mt * 16 + (lane >> 2);
        #pragma unroll
        for (int n8 = 0; n8 < 8; n8++) {
            const int c0 = bn + wn + n8 * 8 + (lane & 3) * 2;
            float2 v0 = make_float2(acc[mt][n8][0], acc[mt][n8][1]);
            float2 v1 = make_float2(acc[mt][n8][2], acc[mt][n8][3]);
            if (mode == 1) {
                float b0 = bq[c0], b1 = bq[c0 + 1];
                v0.x = (v0.x + b0) * QSCALE_C; v0.y = (v0.y + b1) * QSCALE_C;
                v1.x = (v1.x + b0) * QSCALE_C; v1.y = (v1.y + b1) * QSCALE_C;
            }
            *(uint32_t*)(O + (size_t)r0 * N + c0)       = packh(v0.x, v0.y);
            *(uint32_t*)(O + (size_t)(r0 + 8) * N + c0) = packh(v1.x, v1.y);
        }
    }
}

// ---------------------------------------------------------------------------
// Merged k+v kernel: [0,512) k, [512,1024) v. Kp = LDD (single term).
// ---------------------------------------------------------------------------
__global__ void __launch_bounds__(128, 2) kv_kernel(
    const __half* __restrict__ klath, const __half* __restrict__ vlath,
    const __half* __restrict__ wkh,   const __half* __restrict__ wvh,
    __half* __restrict__ kh, __half* __restrict__ vh)
{
    extern __shared__ char dsm[];
    const uint32_t tbase = (smem_u32(dsm) + 1023u) & ~1023u;
    const int tid  = threadIdx.x;
    const int wid  = tid >> 5;
    const int lane = tid & 31;

    const __half *A, *B;
    __half* O;
    int t = blockIdx.x;
    if (t < 512) { A = klath; B = wkh; O = kh; }
    else         { A = vlath; B = wvh; O = vh; t -= 512; }
    const int bm = (t >> 4) * 128;
    const int bn = (t & 15) * 128;
    const int N = 2048;

    float acc[4][8][4];
    ACC_INIT(acc);
    gemm_core(A, B, LDD, bm, bn, tid, wid, lane, tbase, acc);

    const int wm = (wid & 1) * 64;
    const int wn = (wid >> 1) * 64;
    #pragma unroll
    for (int mt = 0; mt < 4; mt++) {
        const int r0 = bm + wm + mt * 16 + (lane >> 2);
        #pragma unroll
        for (int n8 = 0; n8 < 8; n8++) {
            const int c0 = bn + wn + n8 * 8 + (lane & 3) * 2;
            *(uint32_t*)(O + (size_t)r0 * N + c0)       = packh(acc[mt][n8][0], acc[mt][n8][1]);
            *(uint32_t*)(O + (size_t)(r0 + 8) * N + c0) = packh(acc[mt][n8][2], acc[mt][n8][3]);
        }
    }
}

// ---------------------------------------------------------------------------
// Output projection: out = oh @ woh^T + bo (fp32 out), Kp = HH
// ---------------------------------------------------------------------------
__global__ void __launch_bounds__(128, 2) wo_kernel(
    const __half* __restrict__ oh, const __half* __restrict__ woh,
    const float* __restrict__ bo, float* __restrict__ C)
{
    extern __shared__ char dsm[];
    const uint32_t tbase = (smem_u32(dsm) + 1023u) & ~1023u;
    const int tid  = threadIdx.x;
    const int wid  = tid >> 5;
    const int lane = tid & 31;
    const int bm = blockIdx.y * 128;
    const int bn = blockIdx.x * 128;
    const int N = 2048;

    float acc[4][8][4];
    ACC_INIT(acc);
    gemm_core(oh, woh, HH, bm, bn, tid, wid, lane, tbase, acc);

    const int wm = (wid & 1) * 64;
    const int wn = (wid >> 1) * 64;
    #pragma unroll
    for (int mt = 0; mt < 4; mt++) {
        const int r0 = bm + wm + mt * 16 + (lane >> 2);
        #pragma unroll
        for (int n8 = 0; n8 < 8; n8++) {
            const int c0 = bn + wn + n8 * 8 + (lane & 3) * 2;
            float b0 = bo[c0], b1 = bo[c0 + 1];
            float2 v0 = make_float2(acc[mt][n8][0] + b0, acc[mt][n8][1] + b1);
            float2 v1 = make_float2(acc[mt][n8][2] + b0, acc[mt][n8][3] + b1);
            *(float2*)(C + (size_t)r0 * N + c0)       = v0;
            *(float2*)(C + (size_t)(r0 + 8) * N + c0) = v1;
        }
    }
}

// ---------------------------------------------------------------------------
// Merged conversion kernel (single launch):
// blocks [0,12288): weight transpose+cast fp32 [K,N] -> fp16 [N,K]
// blocks [12288,16384): x cast fp32 -> fp16 (streaming, fills idle slots)
// ---------------------------------------------------------------------------
__global__ void convert_kernel(
    const float* __restrict__ x,
    const float* __restrict__ wq, const float* __restrict__ wklat,
    const float* __restrict__ wvlat, const float* __restrict__ wk,
    const float* __restrict__ wv, const float* __restrict__ wo,
    __half* __restrict__ xh,
    __half* __restrict__ wqh, __half* __restrict__ wklath,
    __half* __restrict__ wvlath, __half* __restrict__ wkh,
    __half* __restrict__ wvh, __half* __restrict__ woh)
{
    __shared__ float t[32][33];
    int l = blockIdx.x;
    const int tid = threadIdx.y * 32 + threadIdx.x;   // 0..255

    if (l >= 12288) {
        // x cast: 4096 blocks x 256 thr x 4 float2 = 4M float2 (= 8M floats)
        int base = (l - 12288) * 1024 + tid;
        #pragma unroll
        for (int i = 0; i < 4; i++) {
            int i2 = base + i * 256;
            float2 v = ((const float2*)x)[i2];
            ((__half2*)xh)[i2] = __floats2half2_rn(v.x, v.y);
        }
        return;
    }

    const float* in; __half* out; int K, N, tt;
    if (l < 4096)      { in = wq;    out = wqh;    K = 2048; N = 2048; tt = l; }
    else if (l < 5120) { in = wklat; out = wklath; K = 2048; N = 512;  tt = l - 4096; }
    else if (l < 6144) { in = wvlat; out = wvlath; K = 2048; N = 512;  tt = l - 5120; }
    else if (l < 7168) { in = wk;    out = wkh;    K = 512;  N = 2048; tt = l - 6144; }
    else if (l < 8192) { in = wv;    out = wvh;    K = 512;  N = 2048; tt = l - 7168; }
    else               { in = wo;    out = woh;    K = 2048; N = 2048; tt = l - 8192; }
    int nnb = N >> 5;
    int k0 = (tt / nnb) * 32, n0 = (tt % nnb) * 32;
    int tx = threadIdx.x, ty = threadIdx.y;
    #pragma unroll
    for (int i = 0; i < 32; i += 8)
        t[ty + i][tx] = in[(size_t)(k0 + ty + i) * N + n0 + tx];
    __syncthreads();
    #pragma unroll
    for (int i = 0; i < 32; i += 8) {
        int n = ty + i;
        out[(size_t)(n0 + n) * K + k0 + tx] = __float2half_rn(t[tx][n]);
    }
}

// ---------------------------------------------------------------------------
// Tensor-core flash attention (causal), fp16, TQ=64, 128 thr = 4 warps x 16
// q-rows, single K/V buffer, 2 CTAs/SM (round-15 proven structure).
// smem: Qh(16K) + Kh(32K) + Vh(32K) = 80KB per CTA.
// ---------------------------------------------------------------------------
#define SM_QH 0u
#define SM_KH 16384u
#define SM_VH 49152u

__global__ void __launch_bounds__(128, 2) mla_attn_tc_kernel(
    const __half* __restrict__ Qh,
    const __half* __restrict__ Kh, const __half* __restrict__ Vh,
    __half* __restrict__ Oh)
{
    extern __shared__ char dsm[];
    const uint32_t sb = smem_u32(dsm);

    const int tid  = threadIdx.x;
    const int lane = tid & 31;
    const int w    = tid >> 5;            // 0..3
    const int bh   = blockIdx.y;
    const int b    = bh >> 4;
    const int h    = bh & 15;
    const int qt   = gridDim.x - 1 - blockIdx.x;   // heavy tiles first

    const size_t qrow0 = (size_t)b * SS + (size_t)qt * 64;
    const size_t hcol  = (size_t)h * HDD;
    const int ktmax = ((qt + 1) * 64 - 1) >> 7;    // last k-tile (128-wide)

    // prologue: load Q (64 rows x 128 cols = 1024 16B chunks)
    #pragma unroll
    for (int i = 0; i < 8; i++) {
        int idx = tid + 128 * i;          // 0..1023
        int r   = idx >> 4;               // 0..63
        int d   = (idx & 15) * 8;
        uint32_t off = (uint32_t)(d >> 6) * 8192u
                     + SWZ128((uint32_t)(r * 128 + (d & 63) * 2));
        cp_async16(sb + SM_QH + off, Qh + (qrow0 + r) * HH + hcol + d);
    }
    CP_COMMIT();

    float m2[2] = {-1e30f, -1e30f};
    float l2[2] = {0.f, 0.f};
    float ov[16][4];
    #pragma unroll
    for (int j = 0; j < 16; j++)
        ov[j][0] = ov[j][1] = ov[j][2] = ov[j][3] = 0.f;

    const int a_row  = 16 * w + (lane & 15);       // < 64
    const int a_ch   = lane >> 4;
    const int b_rowb = ((lane >> 4) << 3) + (lane & 7);
    const int b_ch   = (lane >> 3) & 1;
    const int v_row  = (lane & 7) + ((lane >> 3) & 1) * 8;
    const int qlocA  = 16 * w + (lane >> 2);
    const int qgA    = qt * 64 + qlocA;            // global q row (A); B = +8

    for (int kt = 0; kt <= ktmax; kt++) {
        __syncthreads();   // all warps done with previous K/V contents

        // load K/V tile kt (128 rows x 128 cols = 2048 16B chunks each)
        const size_t krow0 = (size_t)b * SS + (size_t)kt * 128;
        #pragma unroll
        for (int i = 0; i < 16; i++) {
            int idx = tid + 128 * i;      // 0..2047
            int r   = idx >> 4;           // 0..127
            int d   = (idx & 15) * 8;
            uint32_t off = (uint32_t)(d >> 6) * 16384u
                         + SWZ128((uint32_t)(r * 128 + (d & 63) * 2));
            const size_t src = (krow0 + r) * HH + hcol + d;
            cp_async16(sb + SM_KH + off, Kh + src);
            cp_async16(sb + SM_VH + off, Vh + src);
        }
        CP_COMMIT();
        CP_WAIT0();        // also covers the Q prologue on kt==0
        __syncthreads();

        // ---- scores: S = Qh·Kh^T  (Q subtiles 64x64, 8KB-strided) ----
        float sc[16][4];
        #pragma unroll
        for (int j = 0; j < 16; j++)
            sc[j][0] = sc[j][1] = sc[j][2] = sc[j][3] = 0.f;

        #pragma unroll
        for (int kc = 0; kc < 8; kc++) {
            uint32_t ah[4];
            {
                int ch = (2 * (kc & 3) + a_ch) ^ (a_row & 7);
                uint32_t off = (uint32_t)(kc >> 2) * 8192u
                             + (uint32_t)(a_row * 128 + ch * 16);
                ldsm_x4(ah, sb + SM_QH + off);
            }
            #pragma unroll
            for (int half = 0; half < 2; half++) {
                uint32_t bh4[4][4];
                #pragma unroll
                for (int nt4 = 0; nt4 < 4; nt4++) {
                    int row = (half * 4 + nt4) * 16 + b_rowb;
                    int ch = (2 * (kc & 3) + b_ch) ^ (row & 7);
                    uint32_t off = (uint32_t)(kc >> 2) * 16384u
                                 + (uint32_t)(row * 128 + ch * 16);
                    ldsm_x4(bh4[nt4], sb + SM_KH + off);
                }
                #pragma unroll
                for (int nt4 = 0; nt4 < 4; nt4++) {
                    int j0 = (half * 4 + nt4) * 2;
                    mma_f16(sc[j0],     ah, &bh4[nt4][0]);
                    mma_f16(sc[j0 + 1], ah, &bh4[nt4][2]);
                }
            }
        }

        // ---- causal mask (last tile only; global col vs global row) ----
        if (kt == ktmax) {
            #pragma unroll
            for (int j = 0; j < 16; j++) {
                int kkg = kt * 128 + 8 * j + 2 * (lane & 3);
                #pragma unroll
                for (int c = 0; c < 2; c++) {
                    if (kkg + c > qgA)     sc[j][c]     = -1e30f;
                    if (kkg + c > qgA + 8) sc[j][2 + c] = -1e30f;
                }
            }
        }

        // ---- online softmax (base-2 domain) ----
        {
            float mA = -1e30f, mB = -1e30f;
            #pragma unroll
            for (int j = 0; j < 16; j++) {
                mA = fmaxf(mA, fmaxf(sc[j][0], sc[j][1]));
                mB = fmaxf(mB, fmaxf(sc[j][2], sc[j][3]));
            }
            mA = fmaxf(mA, __shfl_xor_sync(0xffffffffu, mA, 1));
            mA = fmaxf(mA, __shfl_xor_sync(0xffffffffu, mA, 2));
            mB = fmaxf(mB, __shfl_xor_sync(0xffffffffu, mB, 1));
            mB = fmaxf(mB, __shfl_xor_sync(0xffffffffu, mB, 2));
            float nmA = fmaxf(m2[0], mA), nmB = fmaxf(m2[1], mB);
            float aA = exp2p(m2[0] - nmA), aB = exp2p(m2[1] - nmB);
            float sA = 0.f, sB = 0.f;
            #pragma unroll
            for (int j = 0; j < 16; j++) {
                sc[j][0] = exp2p(sc[j][0] - nmA);
                sc[j][1] = exp2p(sc[j][1] - nmA);
                sc[j][2] = exp2p(sc[j][2] - nmB);
                sc[j][3] = exp2p(sc[j][3] - nmB);
                sA += sc[j][0] + sc[j][1];
                sB += sc[j][2] + sc[j][3];
            }
            sA += __shfl_xor_sync(0xffffffffu, sA, 1);
            sA += __shfl_xor_sync(0xffffffffu, sA, 2);
            sB += __shfl_xor_sync(0xffffffffu, sB, 1);
            sB += __shfl_xor_sync(0xffffffffu, sB, 2);
            l2[0] = l2[0] * aA + sA;
            l2[1] = l2[1] * aB + sB;
            m2[0] = nmA; m2[1] = nmB;
            #pragma unroll
            for (int j = 0; j < 16; j++) {
                ov[j][0] *= aA; ov[j][1] *= aA;
                ov[j][2] *= aB; ov[j][3] *= aB;
            }
        }

        // ---- O += Ph·Vh ----
        #pragma unroll
        for (int kc = 0; kc < 8; kc++) {
            int j0 = 2 * kc;
            uint32_t ph[4];
            #pragma unroll
            for (int u = 0; u < 2; u++)
                #pragma unroll
                for (int t = 0; t < 2; t++)
                    ph[2 * u + t] = packh(sc[j0 + u][2 * t], sc[j0 + u][2 * t + 1]);
            #pragma unroll
            for (int dt = 0; dt < 8; dt++) {
                uint32_t vh4[4];
                int row = kc * 16 + v_row;
                int dloc = (dt * 16) & 63;
                int ch = ((dloc >> 3) + (lane >> 4)) ^ (row & 7);
                uint32_t off = (uint32_t)(dt >> 2) * 16384u
                             + (uint32_t)(row * 128 + ch * 16);
                ldsm_x4_trans(vh4, sb + SM_VH + off);
                int oj = 2 * dt;
                mma_f16(ov[oj],     ph, &vh4[0]);
                mma_f16(ov[oj + 1], ph, &vh4[2]);
            }
        }
    }

    // ---- epilogue: normalize and write oh ----
    {
        float i0 = 1.f / l2[0], i1 = 1.f / l2[1];
        size_t rA = qrow0 + qlocA;
        __half* row0 = Oh + rA * (size_t)HH + hcol;
        __half* row1 = Oh + (rA + 8) * (size_t)HH + hcol;
        #pragma unroll
        for (int j = 0; j < 16; j++) {
            int c = 8 * j + 2 * (lane & 3);
            *(uint32_t*)(row0 + c) = packh(ov[j][0] * i0, ov[j][1] * i0);
            *(uint32_t*)(row1 + c) = packh(ov[j][2] * i1, ov[j][3] * i1);
        }
    }
}

// ---------------------------------------------------------------------------
// launch
// ---------------------------------------------------------------------------
extern "C" void kernel_launch(void* const* d_in, const int* in_sizes, int n_in,
                              void* d_out, int out_size)
{
    (void)in_sizes; (void)n_in; (void)out_size;
    const float* x      = (const float*)d_in[0];
    const float* wq     = (const float*)d_in[1];
    const float* bq     = (const float*)d_in[2];
    const float* wk_lat = (const float*)d_in[3];
    const float* wv_lat = (const float*)d_in[4];
    const float* wk     = (const float*)d_in[5];
    const float* wv     = (const float*)d_in[6];
    const float* wo     = (const float*)d_in[7];
    const float* bo     = (const float*)d_in[8];
    float* out = (float*)d_out;

    __half *qh, *kh, *vh, *oh, *xh;
    cudaGetSymbolAddress((void**)&qh, g_qh);
    cudaGetSymbolAddress((void**)&kh, g_kh);
    cudaGetSymbolAddress((void**)&vh, g_vh);
    cudaGetSymbolAddress((void**)&oh, g_oh);
    cudaGetSymbolAddress((void**)&xh, g_xh);

    __half *klath, *vlath, *wqh, *woh, *wklath, *wvlath, *wkh, *wvh;
    cudaGetSymbolAddress((void**)&klath,  g_klath);
    cudaGetSymbolAddress((void**)&vlath,  g_vlath);
    cudaGetSymbolAddress((void**)&wqh,    g_wqh);
    cudaGetSymbolAddress((void**)&woh,    g_woh);
    cudaGetSymbolAddress((void**)&wklath, g_wklath);
    cudaGetSymbolAddress((void**)&wvlath, g_wvlath);
    cudaGetSymbolAddress((void**)&wkh,    g_wkh);
    cudaGetSymbolAddress((void**)&wvh,    g_wvh);

    const int smem_gemm = 3 * 32768 + 1024;
    cudaFuncSetAttribute(proj_kernel,
                         cudaFuncAttributeMaxDynamicSharedMemorySize, smem_gemm);
    cudaFuncSetAttribute(kv_kernel,
                         cudaFuncAttributeMaxDynamicSharedMemorySize, smem_gemm);
    cudaFuncSetAttribute(wo_kernel,
                         cudaFuncAttributeMaxDynamicSharedMemorySize, smem_gemm);
    const int smem_attn = 80 * 1024;          // Qh + Kh + Vh, 2 CTAs/SM
    cudaFuncSetAttribute(mla_attn_tc_kernel,
                         cudaFuncAttributeMaxDynamicSharedMemorySize, smem_attn);

    // ---- merged input conversions (one launch) ----
    convert_kernel<<<16384, dim3(32, 8)>>>(
        x, wq, wk_lat, wv_lat, wk, wv, wo,
        xh, wqh, wklath, wvlath, wkh, wvh, woh);

    // ---- merged projections: q + klat + vlat (K = 2048) ----
    proj_kernel<<<768, 128, smem_gemm>>>(
        xh, wqh, wklath, wvlath, bq, qh, klath, vlath);

    // ---- merged k + v (K = 512) ----
    kv_kernel<<<1024, 128, smem_gemm>>>(klath, vlath, wkh, wvh, kh, vh);

    // ---- attention (TQ=64, 2 CTAs/SM, round-15 structure) ----
    mla_attn_tc_kernel<<<dim3(SS / 64, BB * NHH), 128, smem_attn>>>(
        qh, kh, vh, oh);

    // ---- output projection (K = 2048) ----
    wo_kernel<<<dim3(HH / 128, MM / 128), 128, smem_gemm>>>(oh, woh, bo, out);
}